// round 1
// baseline (speedup 1.0000x reference)
#include <cuda_runtime.h>
#include <cstdint>

#define MAXN 100000
#define MAXE 1600000

// Scratch (static __device__ allocations are allowed)
__device__ float g_h1[MAXN * 128];     // x @ W1
__device__ float g_out1[MAXN * 128];   // aggregated layer-1 (pre-relu)
__device__ float g_h2[MAXN * 64];      // relu(out1+b1) @ W2
__device__ float g_norm[MAXE];         // per-edge dinv[s]*dinv[d]
__device__ float g_dinv[MAXN];
__device__ int   g_deg[MAXN];

// ---------------------------------------------------------------------------
// degree / normalization
// ---------------------------------------------------------------------------
__global__ void k_deg_init(int n) {
    int i = blockIdx.x * blockDim.x + threadIdx.x;
    if (i < n) g_deg[i] = 1;  // self loop
}

__global__ void k_deg_count(const int* __restrict__ dst, int E) {
    int i = blockIdx.x * blockDim.x + threadIdx.x;
    if (i < E) atomicAdd(&g_deg[dst[i]], 1);
}

__global__ void k_dinv(int n) {
    int i = blockIdx.x * blockDim.x + threadIdx.x;
    if (i < n) g_dinv[i] = rsqrtf((float)g_deg[i]);
}

__global__ void k_norm(const int* __restrict__ src, const int* __restrict__ dst, int E) {
    int i = blockIdx.x * blockDim.x + threadIdx.x;
    if (i < E) g_norm[i] = g_dinv[src[i]] * g_dinv[dst[i]];
}

// ---------------------------------------------------------------------------
// GEMM: C[n x NOUT] = A[n x 128] @ B[128 x NOUT]
// If RELU: A element = max(A + bias[k], 0) applied on load (fuses relu+b1)
// Block: 256 threads, 64 rows per block, full N in smem.
// ---------------------------------------------------------------------------
template <int NOUT, bool RELU>
__global__ void gemm_kernel(const float* __restrict__ A, const float* __restrict__ B,
                            const float* __restrict__ bias, float* __restrict__ C, int n) {
    extern __shared__ float sm[];
    float* As = sm;                // 64 * 128
    float* Bs = sm + 64 * 128;     // 128 * NOUT

    const int t = threadIdx.x;
    const int row0 = blockIdx.x * 64;

    // Load B tile (whole matrix)
    constexpr int B4 = 128 * NOUT / 4;
    for (int i = t; i < B4; i += 256)
        ((float4*)Bs)[i] = ((const float4*)B)[i];

    // Load A tile (64 x 128), optional relu(x + bias)
    for (int i = t; i < 64 * 32; i += 256) {
        int r = i >> 5, c4 = i & 31;
        int gr = row0 + r;
        float4 v = make_float4(0.f, 0.f, 0.f, 0.f);
        if (gr < n) v = ((const float4*)(A + (size_t)gr * 128))[c4];
        if (RELU) {
            float4 bb = ((const float4*)bias)[c4];
            v.x = fmaxf(v.x + bb.x, 0.f);
            v.y = fmaxf(v.y + bb.y, 0.f);
            v.z = fmaxf(v.z + bb.z, 0.f);
            v.w = fmaxf(v.w + bb.w, 0.f);
        }
        ((float4*)As)[i] = v;
    }
    __syncthreads();

    constexpr int TC = NOUT / 16;            // cols per thread (8 or 4)
    const int ty = t >> 4;                   // 0..15 -> rows ty*4 .. +3
    const int tx = t & 15;                   // 0..15 -> cols tx*TC .. +TC-1

    float acc[4][TC];
#pragma unroll
    for (int j = 0; j < 4; j++)
#pragma unroll
        for (int c = 0; c < TC; c++) acc[j][c] = 0.f;

#pragma unroll 4
    for (int k = 0; k < 128; k++) {
        float a[4];
#pragma unroll
        for (int j = 0; j < 4; j++) a[j] = As[(ty * 4 + j) * 128 + k];
        float bv[TC];
#pragma unroll
        for (int c = 0; c < TC; c++) bv[c] = Bs[k * NOUT + tx * TC + c];
#pragma unroll
        for (int j = 0; j < 4; j++)
#pragma unroll
            for (int c = 0; c < TC; c++) acc[j][c] += a[j] * bv[c];
    }

#pragma unroll
    for (int j = 0; j < 4; j++) {
        int gr = row0 + ty * 4 + j;
        if (gr < n) {
            float4* cp = (float4*)(C + (size_t)gr * NOUT + tx * TC);
#pragma unroll
            for (int c4 = 0; c4 < TC / 4; c4++)
                cp[c4] = make_float4(acc[j][c4 * 4 + 0], acc[j][c4 * 4 + 1],
                                     acc[j][c4 * 4 + 2], acc[j][c4 * 4 + 3]);
        }
    }
}

// ---------------------------------------------------------------------------
// Accumulator init with self-loop: out = h * dinv^2   (FEAT4 float4s per node)
// ---------------------------------------------------------------------------
template <int FEAT4>
__global__ void k_self_init(const float* __restrict__ h, float* __restrict__ out, int n) {
    int i = blockIdx.x * blockDim.x + threadIdx.x;
    if (i >= n * FEAT4) return;
    int node = i / FEAT4;
    float d = g_dinv[node];
    float s = d * d;
    float4 v = ((const float4*)h)[i];
    v.x *= s; v.y *= s; v.z *= s; v.w *= s;
    ((float4*)out)[i] = v;
}

// ---------------------------------------------------------------------------
// Edge scatter, layer 1: warp per edge, 128 floats (lane = one float4)
// ---------------------------------------------------------------------------
__device__ __forceinline__ void red_add_v4(float* p, float x, float y, float z, float w) {
    asm volatile("red.global.add.v4.f32 [%0], {%1,%2,%3,%4};"
                 :: "l"(p), "f"(x), "f"(y), "f"(z), "f"(w) : "memory");
}

__global__ void k_scatter128(const int* __restrict__ src, const int* __restrict__ dst,
                             const float* __restrict__ h, float* __restrict__ out, int E) {
    int w = (blockIdx.x * blockDim.x + threadIdx.x) >> 5;
    int lane = threadIdx.x & 31;
    if (w >= E) return;
    int s = __ldg(&src[w]);
    int d = __ldg(&dst[w]);
    float nm = __ldg(&g_norm[w]);
    float4 v = ((const float4*)(h + (size_t)s * 128))[lane];
    float* p = out + (size_t)d * 128 + lane * 4;
    red_add_v4(p, v.x * nm, v.y * nm, v.z * nm, v.w * nm);
}

// Edge scatter, layer 2: half-warp per edge, 64 floats
__global__ void k_scatter64(const int* __restrict__ src, const int* __restrict__ dst,
                            const float* __restrict__ h, float* __restrict__ out, int E) {
    int hw = (blockIdx.x * blockDim.x + threadIdx.x) >> 4;
    int lane = threadIdx.x & 15;
    if (hw >= E) return;
    int s = __ldg(&src[hw]);
    int d = __ldg(&dst[hw]);
    float nm = __ldg(&g_norm[hw]);
    float4 v = ((const float4*)(h + (size_t)s * 64))[lane];
    float* p = out + (size_t)d * 64 + lane * 4;
    red_add_v4(p, v.x * nm, v.y * nm, v.z * nm, v.w * nm);
}

// ---------------------------------------------------------------------------
// log_softmax over 64 classes (+ b2), warp per node, in-place on out
// ---------------------------------------------------------------------------
__global__ void k_logsoftmax(float* __restrict__ out, const float* __restrict__ b2, int n) {
    int w = (blockIdx.x * blockDim.x + threadIdx.x) >> 5;
    int lane = threadIdx.x & 31;
    if (w >= n) return;
    float* row = out + (size_t)w * 64;
    float v0 = row[lane] + b2[lane];
    float v1 = row[lane + 32] + b2[lane + 32];
    float m = fmaxf(v0, v1);
#pragma unroll
    for (int o = 16; o; o >>= 1) m = fmaxf(m, __shfl_xor_sync(0xFFFFFFFFu, m, o));
    float sum = __expf(v0 - m) + __expf(v1 - m);
#pragma unroll
    for (int o = 16; o; o >>= 1) sum += __shfl_xor_sync(0xFFFFFFFFu, sum, o);
    float lse = __logf(sum) + m;
    row[lane] = v0 - lse;
    row[lane + 32] = v1 - lse;
}

// ---------------------------------------------------------------------------
extern "C" void kernel_launch(void* const* d_in, const int* in_sizes, int n_in,
                              void* d_out, int out_size) {
    const float* x  = (const float*)d_in[0];
    const float* W1 = (const float*)d_in[1];
    const float* b1 = (const float*)d_in[2];
    const float* W2 = (const float*)d_in[3];
    const float* b2 = (const float*)d_in[4];
    const int*   ei = (const int*)d_in[5];

    const int n = in_sizes[0] / 128;
    const int E = in_sizes[5] / 2;
    const int* src = ei;
    const int* dst = ei + E;
    float* out = (float*)d_out;

    float* h1   = nullptr; cudaGetSymbolAddress((void**)&h1, g_h1);
    float* out1 = nullptr; cudaGetSymbolAddress((void**)&out1, g_out1);
    float* h2   = nullptr; cudaGetSymbolAddress((void**)&h2, g_h2);

    const int T = 256;

    // opt-in large dynamic smem for the GEMMs
    static int smem_set = 0;
    cudaFuncSetAttribute(gemm_kernel<128, false>,
                         cudaFuncAttributeMaxDynamicSharedMemorySize, (64*128 + 128*128) * 4);
    cudaFuncSetAttribute(gemm_kernel<64, true>,
                         cudaFuncAttributeMaxDynamicSharedMemorySize, (64*128 + 128*64) * 4);
    (void)smem_set;

    // normalization coefficients
    k_deg_init<<<(n + T - 1) / T, T>>>(n);
    k_deg_count<<<(E + T - 1) / T, T>>>(dst, E);
    k_dinv<<<(n + T - 1) / T, T>>>(n);
    k_norm<<<(E + T - 1) / T, T>>>(src, dst, E);

    // layer 1
    gemm_kernel<128, false><<<(n + 63) / 64, T, (64*128 + 128*128) * 4>>>(x, W1, nullptr, h1, n);
    k_self_init<32><<<(n * 32 + T - 1) / T, T>>>(h1, out1, n);
    k_scatter128<<<(E * 32 + T - 1) / T, T>>>(src, dst, h1, out1, E);

    // layer 2 (relu + b1 fused into GEMM A-load)
    gemm_kernel<64, true><<<(n + 63) / 64, T, (64*128 + 128*64) * 4>>>(out1, W2, b1, h2, n);
    k_self_init<16><<<(n * 16 + T - 1) / T, T>>>(h2, out, n);
    k_scatter64<<<(E * 16 + T - 1) / T, T>>>(src, dst, h2, out, E);

    // epilogue
    k_logsoftmax<<<(n * 32 + T - 1) / T, T>>>(out, b2, n);
}

// round 5
// speedup vs baseline: 1.4117x; 1.4117x over previous
#include <cuda_runtime.h>
#include <cstdint>

#define MAXN 100000
#define MAXE 1600000

// Scratch
__device__ float g_h1[MAXN * 128];     // x @ W1
__device__ float g_out1[MAXN * 128];   // relu(aggregate(h1) + b1)
__device__ float g_h2[MAXN * 64];      // out1 @ W2
__device__ float g_dinv[MAXN];
__device__ int   g_deg[MAXN];
__device__ int   g_off[MAXN + 1];
__device__ int   g_cur[MAXN];
__device__ int   g_blk[256];
__device__ int   g_csr[MAXE];          // source node per CSR slot
__device__ float g_csn[MAXE];          // dinv[source] per CSR slot

// ---------------------------------------------------------------------------
// CSR construction
// ---------------------------------------------------------------------------
__global__ void k_hist(const int* __restrict__ dst, int E) {
    int i = blockIdx.x * blockDim.x + threadIdx.x;
    if (i < E) atomicAdd(&g_deg[dst[i]], 1);
}

__global__ void k_dinv(int n) {
    int i = blockIdx.x * blockDim.x + threadIdx.x;
    if (i < n) g_dinv[i] = rsqrtf((float)(g_deg[i] + 1));  // +1 self loop
}

// block-wise exclusive scan (1024 elems/block), block totals to g_blk
__global__ void k_scan1(int n) {
    __shared__ int sh[1024];
    int t = threadIdx.x;
    int i = blockIdx.x * 1024 + t;
    int v = (i < n) ? g_deg[i] : 0;
    sh[t] = v;
    __syncthreads();
    for (int o = 1; o < 1024; o <<= 1) {
        int x = (t >= o) ? sh[t - o] : 0;
        __syncthreads();
        sh[t] += x;
        __syncthreads();
    }
    if (i < n) g_off[i] = sh[t] - v;         // exclusive within block
    if (t == 1023) g_blk[blockIdx.x] = sh[t];
}

// scan the (<=128) block totals
__global__ void k_scan2(int nb) {
    __shared__ int sh[128];
    int t = threadIdx.x;
    int v = (t < nb) ? g_blk[t] : 0;
    sh[t] = v;
    __syncthreads();
    for (int o = 1; o < 128; o <<= 1) {
        int x = (t >= o) ? sh[t - o] : 0;
        __syncthreads();
        sh[t] += x;
        __syncthreads();
    }
    if (t < nb) g_blk[t] = sh[t] - v;        // exclusive
}

__global__ void k_scan3(int n, int E) {
    int i = blockIdx.x * blockDim.x + threadIdx.x;
    if (i < n) {
        int o = g_off[i] + g_blk[i >> 10];
        g_off[i] = o;
        g_cur[i] = o;
    }
    if (i == 0) g_off[n] = E;
}

__global__ void k_fill(const int* __restrict__ src, const int* __restrict__ dst, int E) {
    int i = blockIdx.x * blockDim.x + threadIdx.x;
    if (i < E) {
        int s = src[i];
        int d = dst[i];
        int pos = atomicAdd(&g_cur[d], 1);
        g_csr[pos] = s;
        g_csn[pos] = g_dinv[s];
    }
}

// ---------------------------------------------------------------------------
// GEMM: C[n x NOUT] = A[n x 128] @ B[128 x NOUT]
// ---------------------------------------------------------------------------
template <int NOUT>
__global__ void gemm_kernel(const float* __restrict__ A, const float* __restrict__ B,
                            float* __restrict__ C, int n) {
    extern __shared__ float sm[];
    float* As = sm;                // 64 * 128
    float* Bs = sm + 64 * 128;     // 128 * NOUT

    const int t = threadIdx.x;
    const int row0 = blockIdx.x * 64;

    constexpr int B4 = 128 * NOUT / 4;
    for (int i = t; i < B4; i += 256)
        ((float4*)Bs)[i] = ((const float4*)B)[i];

    for (int i = t; i < 64 * 32; i += 256) {
        int r = i >> 5, c4 = i & 31;
        int gr = row0 + r;
        float4 v = make_float4(0.f, 0.f, 0.f, 0.f);
        if (gr < n) v = ((const float4*)(A + (size_t)gr * 128))[c4];
        ((float4*)As)[i] = v;
    }
    __syncthreads();

    constexpr int TC = NOUT / 16;
    const int ty = t >> 4;
    const int tx = t & 15;

    float acc[4][TC];
#pragma unroll
    for (int j = 0; j < 4; j++)
#pragma unroll
        for (int c = 0; c < TC; c++) acc[j][c] = 0.f;

#pragma unroll 4
    for (int k = 0; k < 128; k++) {
        float a[4];
#pragma unroll
        for (int j = 0; j < 4; j++) a[j] = As[(ty * 4 + j) * 128 + k];
        float bv[TC];
#pragma unroll
        for (int c = 0; c < TC; c++) bv[c] = Bs[k * NOUT + tx * TC + c];
#pragma unroll
        for (int j = 0; j < 4; j++)
#pragma unroll
            for (int c = 0; c < TC; c++) acc[j][c] += a[j] * bv[c];
    }

#pragma unroll
    for (int j = 0; j < 4; j++) {
        int gr = row0 + ty * 4 + j;
        if (gr < n) {
            float4* cp = (float4*)(C + (size_t)gr * NOUT + tx * TC);
#pragma unroll
            for (int c4 = 0; c4 < TC / 4; c4++)
                cp[c4] = make_float4(acc[j][c4 * 4 + 0], acc[j][c4 * 4 + 1],
                                     acc[j][c4 * 4 + 2], acc[j][c4 * 4 + 3]);
        }
    }
}

// ---------------------------------------------------------------------------
// Layer-1 gather: warp per destination node, 128 feats (lane = float4).
// out = relu(aggregate + b1)
// ---------------------------------------------------------------------------
__global__ void k_gather128(const float* __restrict__ h, const float* __restrict__ b1,
                            float* __restrict__ out, int n) {
    int node = blockIdx.x * 8 + (threadIdx.x >> 5);
    int lane = threadIdx.x & 31;
    if (node >= n) return;

    float dd = g_dinv[node];
    float self = dd * dd;
    float4 acc = ((const float4*)(h + (size_t)node * 128))[lane];
    acc.x *= self; acc.y *= self; acc.z *= self; acc.w *= self;

    int e = g_off[node];
    const int end = g_off[node + 1];

    int sN = 0; float wN = 0.f;
    if (e < end) { sN = g_csr[e]; wN = g_csn[e]; }
    while (e < end) {
        int s = sN; float w = wN;
        if (e + 1 < end) { sN = g_csr[e + 1]; wN = g_csn[e + 1]; }
        float4 v = ((const float4*)(h + (size_t)s * 128))[lane];
        float nm = w * dd;
        acc.x += v.x * nm; acc.y += v.y * nm; acc.z += v.z * nm; acc.w += v.w * nm;
        ++e;
    }

    float4 bb = ((const float4*)b1)[lane];
    acc.x = fmaxf(acc.x + bb.x, 0.f);
    acc.y = fmaxf(acc.y + bb.y, 0.f);
    acc.z = fmaxf(acc.z + bb.z, 0.f);
    acc.w = fmaxf(acc.w + bb.w, 0.f);
    ((float4*)(out + (size_t)node * 128))[lane] = acc;
}

// ---------------------------------------------------------------------------
// Layer-2 gather + bias + log_softmax: half-warp per node, 64 feats.
// ---------------------------------------------------------------------------
__global__ void k_gather64_lsm(const float* __restrict__ h, const float* __restrict__ b2,
                               float* __restrict__ out, int n) {
    int node = blockIdx.x * 16 + (threadIdx.x >> 4);
    int lane = threadIdx.x & 15;
    if (node >= n) return;

    float dd = g_dinv[node];
    float self = dd * dd;
    float4 acc = ((const float4*)(h + (size_t)node * 64))[lane];
    acc.x *= self; acc.y *= self; acc.z *= self; acc.w *= self;

    int e = g_off[node];
    const int end = g_off[node + 1];

    int sN = 0; float wN = 0.f;
    if (e < end) { sN = g_csr[e]; wN = g_csn[e]; }
    while (e < end) {
        int s = sN; float w = wN;
        if (e + 1 < end) { sN = g_csr[e + 1]; wN = g_csn[e + 1]; }
        float4 v = ((const float4*)(h + (size_t)s * 64))[lane];
        float nm = w * dd;
        acc.x += v.x * nm; acc.y += v.y * nm; acc.z += v.z * nm; acc.w += v.w * nm;
        ++e;
    }

    float4 bb = ((const float4*)b2)[lane];
    acc.x += bb.x; acc.y += bb.y; acc.z += bb.z; acc.w += bb.w;

    // log_softmax over the 64 values held by this 16-lane group
    float m = fmaxf(fmaxf(acc.x, acc.y), fmaxf(acc.z, acc.w));
#pragma unroll
    for (int o = 8; o; o >>= 1) m = fmaxf(m, __shfl_xor_sync(0xFFFFFFFFu, m, o));
    float sum = __expf(acc.x - m) + __expf(acc.y - m) + __expf(acc.z - m) + __expf(acc.w - m);
#pragma unroll
    for (int o = 8; o; o >>= 1) sum += __shfl_xor_sync(0xFFFFFFFFu, sum, o);
    float lse = __logf(sum) + m;

    float4 r = make_float4(acc.x - lse, acc.y - lse, acc.z - lse, acc.w - lse);
    ((float4*)(out + (size_t)node * 64))[lane] = r;
}

// ---------------------------------------------------------------------------
extern "C" void kernel_launch(void* const* d_in, const int* in_sizes, int n_in,
                              void* d_out, int out_size) {
    const float* x  = (const float*)d_in[0];
    const float* W1 = (const float*)d_in[1];
    const float* b1 = (const float*)d_in[2];
    const float* W2 = (const float*)d_in[3];
    const float* b2 = (const float*)d_in[4];
    const int*   ei = (const int*)d_in[5];

    const int n = in_sizes[0] / 128;
    const int E = in_sizes[5] / 2;
    const int* src = ei;
    const int* dst = ei + E;
    float* out = (float*)d_out;

    float* h1   = nullptr; cudaGetSymbolAddress((void**)&h1, g_h1);
    float* out1 = nullptr; cudaGetSymbolAddress((void**)&out1, g_out1);
    float* h2   = nullptr; cudaGetSymbolAddress((void**)&h2, g_h2);
    int*   degp = nullptr; cudaGetSymbolAddress((void**)&degp, g_deg);

    const int T = 256;
    const int nb = (n + 1023) / 1024;

    cudaFuncSetAttribute(gemm_kernel<128>,
                         cudaFuncAttributeMaxDynamicSharedMemorySize, (64*128 + 128*128) * 4);
    cudaFuncSetAttribute(gemm_kernel<64>,
                         cudaFuncAttributeMaxDynamicSharedMemorySize, (64*128 + 128*64) * 4);

    // CSR build
    cudaMemsetAsync(degp, 0, n * sizeof(int));
    k_hist<<<(E + T - 1) / T, T>>>(dst, E);
    k_dinv<<<(n + T - 1) / T, T>>>(n);
    k_scan1<<<nb, 1024>>>(n);
    k_scan2<<<1, 128>>>(nb);
    k_scan3<<<(n + T - 1) / T, T>>>(n, E);
    k_fill<<<(E + T - 1) / T, T>>>(src, dst, E);

    // layer 1
    gemm_kernel<128><<<(n + 63) / 64, T, (64*128 + 128*128) * 4>>>(x, W1, h1, n);
    k_gather128<<<(n + 7) / 8, T>>>(h1, b1, out1, n);

    // layer 2
    gemm_kernel<64><<<(n + 63) / 64, T, (64*128 + 128*64) * 4>>>(out1, W2, h2, n);
    k_gather64_lsm<<<(n + 15) / 16, T>>>(h2, b2, out, n);
}

// round 7
// speedup vs baseline: 1.8885x; 1.3378x over previous
#include <cuda_runtime.h>
#include <cuda_bf16.h>
#include <cstdint>

#define MAXN 100000
#define MAXE 1600000

// Scratch
__device__ float g_h1[MAXN * 128];
__device__ float g_out1[MAXN * 128];
__device__ float g_h2[MAXN * 64];
__device__ float g_dinv[MAXN];
__device__ int   g_deg[MAXN];
__device__ int   g_off[MAXN + 1];
__device__ int   g_cur[MAXN];
__device__ int   g_blk[256];
__device__ int   g_csr[MAXE];
__device__ float g_csn[MAXE];
// Pre-split, pre-transposed weights: Bt[n][k] packed bf16 (hi and lo of residual)
__device__ __nv_bfloat16 g_w1h[128 * 128];
__device__ __nv_bfloat16 g_w1l[128 * 128];
__device__ __nv_bfloat16 g_w2h[64 * 128];
__device__ __nv_bfloat16 g_w2l[64 * 128];

// ---------------------------------------------------------------------------
// CSR construction
// ---------------------------------------------------------------------------
__global__ void k_hist(const int* __restrict__ dst, int E) {
    int i = blockIdx.x * blockDim.x + threadIdx.x;
    if (i < E) atomicAdd(&g_deg[dst[i]], 1);
}
__global__ void k_dinv(int n) {
    int i = blockIdx.x * blockDim.x + threadIdx.x;
    if (i < n) g_dinv[i] = rsqrtf((float)(g_deg[i] + 1));
}
__global__ void k_scan1(int n) {
    __shared__ int sh[1024];
    int t = threadIdx.x, i = blockIdx.x * 1024 + t;
    int v = (i < n) ? g_deg[i] : 0;
    sh[t] = v;
    __syncthreads();
    for (int o = 1; o < 1024; o <<= 1) {
        int x = (t >= o) ? sh[t - o] : 0;
        __syncthreads();
        sh[t] += x;
        __syncthreads();
    }
    if (i < n) g_off[i] = sh[t] - v;
    if (t == 1023) g_blk[blockIdx.x] = sh[t];
}
__global__ void k_scan2(int nb) {
    __shared__ int sh[128];
    int t = threadIdx.x;
    int v = (t < nb) ? g_blk[t] : 0;
    sh[t] = v;
    __syncthreads();
    for (int o = 1; o < 128; o <<= 1) {
        int x = (t >= o) ? sh[t - o] : 0;
        __syncthreads();
        sh[t] += x;
        __syncthreads();
    }
    if (t < nb) g_blk[t] = sh[t] - v;
}
__global__ void k_scan3(int n, int E) {
    int i = blockIdx.x * blockDim.x + threadIdx.x;
    if (i < n) {
        int o = g_off[i] + g_blk[i >> 10];
        g_off[i] = o;
        g_cur[i] = o;
    }
    if (i == 0) g_off[n] = E;
}
__global__ void k_fill(const int* __restrict__ src, const int* __restrict__ dst, int E) {
    int i = blockIdx.x * blockDim.x + threadIdx.x;
    if (i < E) {
        int s = src[i], d = dst[i];
        int pos = atomicAdd(&g_cur[d], 1);
        g_csr[pos] = s;
        g_csn[pos] = g_dinv[s];
    }
}

// ---------------------------------------------------------------------------
// Weight prep: split fp32 -> bf16 hi + bf16(residual), transposed Bt[n][k].
// W stored [k][n] row-major in input; output packed [n][128].
// ---------------------------------------------------------------------------
__global__ void k_prep_w(const float* __restrict__ W1, const float* __restrict__ W2) {
    int i = blockIdx.x * blockDim.x + threadIdx.x;
    if (i < 128 * 128) {
        int k = i >> 7, nn = i & 127;
        float v = W1[i];
        __nv_bfloat16 h = __float2bfloat16(v);
        __nv_bfloat16 l = __float2bfloat16(v - __bfloat162float(h));
        g_w1h[nn * 128 + k] = h;
        g_w1l[nn * 128 + k] = l;
    } else if (i < 128 * 128 + 128 * 64) {
        int j = i - 128 * 128;
        int k = j >> 6, nn = j & 63;
        float v = W2[j];
        __nv_bfloat16 h = __float2bfloat16(v);
        __nv_bfloat16 l = __float2bfloat16(v - __bfloat162float(h));
        g_w2h[nn * 128 + k] = h;
        g_w2l[nn * 128 + k] = l;
    }
}

// ---------------------------------------------------------------------------
// HMMA GEMM: C[n x NOUT] = A[n x 128] @ W[128 x NOUT]
// bf16 split 3-pass (AhBh + AhBl + AlBh), fp32 accum.
// CTA: 256 threads (8 warps) x 128 rows. Warp = 16 rows x NOUT.
// ---------------------------------------------------------------------------
#define STRIDE_W 68   // words (bf16x2) per row: 64 data + 4 pad -> conflict-free

__device__ __forceinline__ void mma_bf16(float* c, const uint32_t* a, const uint32_t* b) {
    asm volatile(
        "mma.sync.aligned.m16n8k16.row.col.f32.bf16.bf16.f32 "
        "{%0,%1,%2,%3}, {%4,%5,%6,%7}, {%8,%9}, {%0,%1,%2,%3};"
        : "+f"(c[0]), "+f"(c[1]), "+f"(c[2]), "+f"(c[3])
        : "r"(a[0]), "r"(a[1]), "r"(a[2]), "r"(a[3]), "r"(b[0]), "r"(b[1]));
}

template <int NOUT>
__global__ void __launch_bounds__(256)
gemm_mma(const float* __restrict__ A, const __nv_bfloat16* __restrict__ Wh,
         const __nv_bfloat16* __restrict__ Wl, float* __restrict__ C, int n) {
    extern __shared__ uint32_t sm[];
    uint32_t* ASH = sm;                         // 128 rows x 68 words (bf16x2)
    uint32_t* ASL = ASH + 128 * STRIDE_W;
    uint32_t* BSH = ASL + 128 * STRIDE_W;       // NOUT rows x 68 words
    uint32_t* BSL = BSH + NOUT * STRIDE_W;

    const int t = threadIdx.x;
    const int wid = t >> 5, lane = t & 31;
    const int g = lane >> 2, tq = lane & 3;     // group / thread-in-group
    const int row0 = blockIdx.x * 128;

    // Stage B (pre-split packed [n][128] bf16 -> padded words)
    for (int i = t; i < NOUT * 64; i += 256) {
        int r = i >> 6, w = i & 63;
        BSH[r * STRIDE_W + w] = ((const uint32_t*)Wh)[i];
        BSL[r * STRIDE_W + w] = ((const uint32_t*)Wl)[i];
    }
    // Stage A: load fp32, split hi/lo, pack bf16x2
    for (int i = t; i < 128 * 64; i += 256) {
        int r = i >> 6, w = i & 63;
        int gr = row0 + r;
        float2 v = make_float2(0.f, 0.f);
        if (gr < n) v = ((const float2*)(A + (size_t)gr * 128))[w];
        __nv_bfloat16 hx = __float2bfloat16(v.x), hy = __float2bfloat16(v.y);
        __nv_bfloat16 lx = __float2bfloat16(v.x - __bfloat162float(hx));
        __nv_bfloat16 ly = __float2bfloat16(v.y - __bfloat162float(hy));
        uint32_t hw = ((uint32_t)__bfloat16_as_ushort(hy) << 16) | __bfloat16_as_ushort(hx);
        uint32_t lw = ((uint32_t)__bfloat16_as_ushort(ly) << 16) | __bfloat16_as_ushort(lx);
        ASH[r * STRIDE_W + w] = hw;
        ASL[r * STRIDE_W + w] = lw;
    }
    __syncthreads();

    constexpr int NT = NOUT / 8;                // n-tiles per warp
    float acc[NT][4];
#pragma unroll
    for (int i = 0; i < NT; i++)
#pragma unroll
        for (int j = 0; j < 4; j++) acc[i][j] = 0.f;

    const int wrow = wid * 16;                  // warp's row base within tile

#pragma unroll
    for (int kk = 0; kk < 8; kk++) {            // K = 8 x 16
        // A fragments (hi, lo): a0:(row g, k 2tq) a1:(g+8) a2:(g, k 2tq+8) a3:(g+8)
        uint32_t ah[4], al[4];
        int ra = (wrow + g) * STRIDE_W + kk * 8 + tq;
        int rb = (wrow + g + 8) * STRIDE_W + kk * 8 + tq;
        ah[0] = ASH[ra];     ah[1] = ASH[rb];
        ah[2] = ASH[ra + 4]; ah[3] = ASH[rb + 4];
        al[0] = ASL[ra];     al[1] = ASL[rb];
        al[2] = ASL[ra + 4]; al[3] = ASL[rb + 4];

#pragma unroll
        for (int nt = 0; nt < NT; nt++) {
            // B fragments: b0:(col g+8nt, k 2tq) b1:(k 2tq+8)
            int nb = (nt * 8 + g) * STRIDE_W + kk * 8 + tq;
            uint32_t bh[2], bl[2];
            bh[0] = BSH[nb]; bh[1] = BSH[nb + 4];
            bl[0] = BSL[nb]; bl[1] = BSL[nb + 4];
            mma_bf16(acc[nt], ah, bh);
            mma_bf16(acc[nt], ah, bl);
            mma_bf16(acc[nt], al, bh);
        }
    }

    // Epilogue: c0,c1 -> (row g, col 2tq..+1); c2,c3 -> (row g+8)
    int gr0 = row0 + wrow + g;
    int gr1 = gr0 + 8;
#pragma unroll
    for (int nt = 0; nt < NT; nt++) {
        int col = nt * 8 + tq * 2;
        if (gr0 < n)
            *(float2*)(C + (size_t)gr0 * NOUT + col) = make_float2(acc[nt][0], acc[nt][1]);
        if (gr1 < n)
            *(float2*)(C + (size_t)gr1 * NOUT + col) = make_float2(acc[nt][2], acc[nt][3]);
    }
}

// ---------------------------------------------------------------------------
// Layer-1 gather: warp per destination node, 128 feats (lane = float4).
// ---------------------------------------------------------------------------
__global__ void k_gather128(const float* __restrict__ h, const float* __restrict__ b1,
                            float* __restrict__ out, int n) {
    int node = blockIdx.x * 8 + (threadIdx.x >> 5);
    int lane = threadIdx.x & 31;
    if (node >= n) return;

    float dd = g_dinv[node];
    float self = dd * dd;
    float4 acc = ((const float4*)(h + (size_t)node * 128))[lane];
    acc.x *= self; acc.y *= self; acc.z *= self; acc.w *= self;

    int e = g_off[node];
    const int end = g_off[node + 1];
    int sN = 0; float wN = 0.f;
    if (e < end) { sN = g_csr[e]; wN = g_csn[e]; }
    while (e < end) {
        int s = sN; float w = wN;
        if (e + 1 < end) { sN = g_csr[e + 1]; wN = g_csn[e + 1]; }
        float4 v = ((const float4*)(h + (size_t)s * 128))[lane];
        float nm = w * dd;
        acc.x += v.x * nm; acc.y += v.y * nm; acc.z += v.z * nm; acc.w += v.w * nm;
        ++e;
    }

    float4 bb = ((const float4*)b1)[lane];
    acc.x = fmaxf(acc.x + bb.x, 0.f);
    acc.y = fmaxf(acc.y + bb.y, 0.f);
    acc.z = fmaxf(acc.z + bb.z, 0.f);
    acc.w = fmaxf(acc.w + bb.w, 0.f);
    ((float4*)(out + (size_t)node * 128))[lane] = acc;
}

// ---------------------------------------------------------------------------
// Layer-2 gather + bias + log_softmax: half-warp per node, 64 feats.
// ---------------------------------------------------------------------------
__global__ void k_gather64_lsm(const float* __restrict__ h, const float* __restrict__ b2,
                               float* __restrict__ out, int n) {
    int node = blockIdx.x * 16 + (threadIdx.x >> 4);
    int lane = threadIdx.x & 15;
    if (node >= n) return;

    float dd = g_dinv[node];
    float self = dd * dd;
    float4 acc = ((const float4*)(h + (size_t)node * 64))[lane];
    acc.x *= self; acc.y *= self; acc.z *= self; acc.w *= self;

    int e = g_off[node];
    const int end = g_off[node + 1];
    int sN = 0; float wN = 0.f;
    if (e < end) { sN = g_csr[e]; wN = g_csn[e]; }
    while (e < end) {
        int s = sN; float w = wN;
        if (e + 1 < end) { sN = g_csr[e + 1]; wN = g_csn[e + 1]; }
        float4 v = ((const float4*)(h + (size_t)s * 64))[lane];
        float nm = w * dd;
        acc.x += v.x * nm; acc.y += v.y * nm; acc.z += v.z * nm; acc.w += v.w * nm;
        ++e;
    }

    float4 bb = ((const float4*)b2)[lane];
    acc.x += bb.x; acc.y += bb.y; acc.z += bb.z; acc.w += bb.w;

    float m = fmaxf(fmaxf(acc.x, acc.y), fmaxf(acc.z, acc.w));
#pragma unroll
    for (int o = 8; o; o >>= 1) m = fmaxf(m, __shfl_xor_sync(0xFFFFFFFFu, m, o));
    float sum = __expf(acc.x - m) + __expf(acc.y - m) + __expf(acc.z - m) + __expf(acc.w - m);
#pragma unroll
    for (int o = 8; o; o >>= 1) sum += __shfl_xor_sync(0xFFFFFFFFu, sum, o);
    float lse = __logf(sum) + m;

    ((float4*)(out + (size_t)node * 64))[lane] =
        make_float4(acc.x - lse, acc.y - lse, acc.z - lse, acc.w - lse);
}

// ---------------------------------------------------------------------------
extern "C" void kernel_launch(void* const* d_in, const int* in_sizes, int n_in,
                              void* d_out, int out_size) {
    const float* x  = (const float*)d_in[0];
    const float* W1 = (const float*)d_in[1];
    const float* b1 = (const float*)d_in[2];
    const float* W2 = (const float*)d_in[3];
    const float* b2 = (const float*)d_in[4];
    const int*   ei = (const int*)d_in[5];

    const int n = in_sizes[0] / 128;
    const int E = in_sizes[5] / 2;
    const int* src = ei;
    const int* dst = ei + E;
    float* out = (float*)d_out;

    float* h1   = nullptr; cudaGetSymbolAddress((void**)&h1, g_h1);
    float* out1 = nullptr; cudaGetSymbolAddress((void**)&out1, g_out1);
    float* h2   = nullptr; cudaGetSymbolAddress((void**)&h2, g_h2);
    int*   degp = nullptr; cudaGetSymbolAddress((void**)&degp, g_deg);
    __nv_bfloat16 *w1h, *w1l, *w2h, *w2l;
    cudaGetSymbolAddress((void**)&w1h, g_w1h);
    cudaGetSymbolAddress((void**)&w1l, g_w1l);
    cudaGetSymbolAddress((void**)&w2h, g_w2h);
    cudaGetSymbolAddress((void**)&w2l, g_w2l);

    const int T = 256;
    const int nb = (n + 1023) / 1024;

    // smem: (A: 2 * 128*68  +  B: 2 * NOUT*68) words * 4B
    constexpr int SM1 = (2 * 128 * STRIDE_W + 2 * 128 * STRIDE_W) * 4;  // 139264
    constexpr int SM2 = (2 * 128 * STRIDE_W + 2 * 64 * STRIDE_W) * 4;   // 104448
    cudaFuncSetAttribute(gemm_mma<128>, cudaFuncAttributeMaxDynamicSharedMemorySize, SM1);
    cudaFuncSetAttribute(gemm_mma<64>,  cudaFuncAttributeMaxDynamicSharedMemorySize, SM2);

    // CSR build + weight prep
    cudaMemsetAsync(degp, 0, n * sizeof(int));
    k_prep_w<<<(128 * 128 + 128 * 64 + T - 1) / T, T>>>(W1, W2);
    k_hist<<<(E + T - 1) / T, T>>>(dst, E);
    k_dinv<<<(n + T - 1) / T, T>>>(n);
    k_scan1<<<nb, 1024>>>(n);
    k_scan2<<<1, 128>>>(nb);
    k_scan3<<<(n + T - 1) / T, T>>>(n, E);
    k_fill<<<(E + T - 1) / T, T>>>(src, dst, E);

    const int gb = (n + 127) / 128;
    // layer 1
    gemm_mma<128><<<gb, T, SM1>>>(x, w1h, w1l, h1, n);
    k_gather128<<<(n + 7) / 8, T>>>(h1, b1, out1, n);
    // layer 2
    gemm_mma<64><<<gb, T, SM2>>>(out1, w2h, w2l, h2, n);
    k_gather64_lsm<<<(n + 15) / 16, T>>>(h2, b2, out, n);
}

// round 9
// speedup vs baseline: 2.1425x; 1.1345x over previous
#include <cuda_runtime.h>
#include <cuda_bf16.h>
#include <cstdint>

#define MAXN 100000
#define MAXE 1600000

// Scratch
__device__ float g_h1[MAXN * 128];
__device__ float g_out1[MAXN * 128];
__device__ float g_h2[MAXN * 64];
__device__ float g_dinv[MAXN];
__device__ int   g_deg[MAXN];
__device__ int   g_off[MAXN + 1];
__device__ int   g_cur[MAXN];
__device__ int   g_blk[256];
__device__ int   g_csr[MAXE];
__device__ float g_csn[MAXE];
// Pre-split, pre-transposed weights: Bt[n][k] packed bf16 (hi and lo of residual)
__device__ __nv_bfloat16 g_w1h[128 * 128];
__device__ __nv_bfloat16 g_w1l[128 * 128];
__device__ __nv_bfloat16 g_w2h[64 * 128];
__device__ __nv_bfloat16 g_w2l[64 * 128];

// ---------------------------------------------------------------------------
// CSR construction
// ---------------------------------------------------------------------------
__global__ void k_hist(const int* __restrict__ dst, int E) {
    int i = blockIdx.x * blockDim.x + threadIdx.x;
    if (i < E) atomicAdd(&g_deg[dst[i]], 1);
}
__global__ void k_dinv(int n) {
    int i = blockIdx.x * blockDim.x + threadIdx.x;
    if (i < n) g_dinv[i] = rsqrtf((float)(g_deg[i] + 1));
}
__global__ void k_scan1(int n) {
    __shared__ int sh[1024];
    int t = threadIdx.x, i = blockIdx.x * 1024 + t;
    int v = (i < n) ? g_deg[i] : 0;
    sh[t] = v;
    __syncthreads();
    for (int o = 1; o < 1024; o <<= 1) {
        int x = (t >= o) ? sh[t - o] : 0;
        __syncthreads();
        sh[t] += x;
        __syncthreads();
    }
    if (i < n) g_off[i] = sh[t] - v;
    if (t == 1023) g_blk[blockIdx.x] = sh[t];
}
__global__ void k_scan2(int nb) {
    __shared__ int sh[128];
    int t = threadIdx.x;
    int v = (t < nb) ? g_blk[t] : 0;
    sh[t] = v;
    __syncthreads();
    for (int o = 1; o < 128; o <<= 1) {
        int x = (t >= o) ? sh[t - o] : 0;
        __syncthreads();
        sh[t] += x;
        __syncthreads();
    }
    if (t < nb) g_blk[t] = sh[t] - v;
}
__global__ void k_scan3(int n, int E) {
    int i = blockIdx.x * blockDim.x + threadIdx.x;
    if (i < n) {
        int o = g_off[i] + g_blk[i >> 10];
        g_off[i] = o;
        g_cur[i] = o;
    }
    if (i == 0) g_off[n] = E;
}
__global__ void k_fill(const int* __restrict__ src, const int* __restrict__ dst, int E) {
    int i = blockIdx.x * blockDim.x + threadIdx.x;
    if (i < E) {
        int s = src[i], d = dst[i];
        int pos = atomicAdd(&g_cur[d], 1);
        g_csr[pos] = s;
        g_csn[pos] = g_dinv[s];
    }
}

// ---------------------------------------------------------------------------
// Weight prep: split fp32 -> bf16 hi + bf16(residual), transposed Bt[n][k].
// ---------------------------------------------------------------------------
__global__ void k_prep_w(const float* __restrict__ W1, const float* __restrict__ W2) {
    int i = blockIdx.x * blockDim.x + threadIdx.x;
    if (i < 128 * 128) {
        int k = i >> 7, nn = i & 127;
        float v = W1[i];
        __nv_bfloat16 h = __float2bfloat16(v);
        __nv_bfloat16 l = __float2bfloat16(v - __bfloat162float(h));
        g_w1h[nn * 128 + k] = h;
        g_w1l[nn * 128 + k] = l;
    } else if (i < 128 * 128 + 128 * 64) {
        int j = i - 128 * 128;
        int k = j >> 6, nn = j & 63;
        float v = W2[j];
        __nv_bfloat16 h = __float2bfloat16(v);
        __nv_bfloat16 l = __float2bfloat16(v - __bfloat162float(h));
        g_w2h[nn * 128 + k] = h;
        g_w2l[nn * 128 + k] = l;
    }
}

// ---------------------------------------------------------------------------
// HMMA GEMM: C[n x NOUT] = A[n x 128] @ W[128 x NOUT]
// bf16 split 3-pass (AhBh + AhBl + AlBh), fp32 accum.
// ---------------------------------------------------------------------------
#define STRIDE_W 68   // words per row: 64 data + 4 pad -> conflict-free fragments

__device__ __forceinline__ void mma_bf16(float* c, const uint32_t* a, const uint32_t* b) {
    asm volatile(
        "mma.sync.aligned.m16n8k16.row.col.f32.bf16.bf16.f32 "
        "{%0,%1,%2,%3}, {%4,%5,%6,%7}, {%8,%9}, {%0,%1,%2,%3};"
        : "+f"(c[0]), "+f"(c[1]), "+f"(c[2]), "+f"(c[3])
        : "r"(a[0]), "r"(a[1]), "r"(a[2]), "r"(a[3]), "r"(b[0]), "r"(b[1]));
}

template <int NOUT>
__global__ void __launch_bounds__(256)
gemm_mma(const float* __restrict__ A, const __nv_bfloat16* __restrict__ Wh,
         const __nv_bfloat16* __restrict__ Wl, float* __restrict__ C, int n) {
    extern __shared__ uint32_t sm[];
    uint32_t* ASH = sm;
    uint32_t* ASL = ASH + 128 * STRIDE_W;
    uint32_t* BSH = ASL + 128 * STRIDE_W;
    uint32_t* BSL = BSH + NOUT * STRIDE_W;

    const int t = threadIdx.x;
    const int wid = t >> 5, lane = t & 31;
    const int g = lane >> 2, tq = lane & 3;
    const int row0 = blockIdx.x * 128;

    for (int i = t; i < NOUT * 64; i += 256) {
        int r = i >> 6, w = i & 63;
        BSH[r * STRIDE_W + w] = ((const uint32_t*)Wh)[i];
        BSL[r * STRIDE_W + w] = ((const uint32_t*)Wl)[i];
    }
    for (int i = t; i < 128 * 64; i += 256) {
        int r = i >> 6, w = i & 63;
        int gr = row0 + r;
        float2 v = make_float2(0.f, 0.f);
        if (gr < n) v = ((const float2*)(A + (size_t)gr * 128))[w];
        __nv_bfloat16 hx = __float2bfloat16(v.x), hy = __float2bfloat16(v.y);
        __nv_bfloat16 lx = __float2bfloat16(v.x - __bfloat162float(hx));
        __nv_bfloat16 ly = __float2bfloat16(v.y - __bfloat162float(hy));
        uint32_t hw = ((uint32_t)__bfloat16_as_ushort(hy) << 16) | __bfloat16_as_ushort(hx);
        uint32_t lw = ((uint32_t)__bfloat16_as_ushort(ly) << 16) | __bfloat16_as_ushort(lx);
        ASH[r * STRIDE_W + w] = hw;
        ASL[r * STRIDE_W + w] = lw;
    }
    __syncthreads();

    constexpr int NT = NOUT / 8;
    float acc[NT][4];
#pragma unroll
    for (int i = 0; i < NT; i++)
#pragma unroll
        for (int j = 0; j < 4; j++) acc[i][j] = 0.f;

    const int wrow = wid * 16;

#pragma unroll
    for (int kk = 0; kk < 8; kk++) {
        uint32_t ah[4], al[4];
        int ra = (wrow + g) * STRIDE_W + kk * 8 + tq;
        int rb = (wrow + g + 8) * STRIDE_W + kk * 8 + tq;
        ah[0] = ASH[ra];     ah[1] = ASH[rb];
        ah[2] = ASH[ra + 4]; ah[3] = ASH[rb + 4];
        al[0] = ASL[ra];     al[1] = ASL[rb];
        al[2] = ASL[ra + 4]; al[3] = ASL[rb + 4];

#pragma unroll
        for (int nt = 0; nt < NT; nt++) {
            int nb = (nt * 8 + g) * STRIDE_W + kk * 8 + tq;
            uint32_t bh[2], bl[2];
            bh[0] = BSH[nb]; bh[1] = BSH[nb + 4];
            bl[0] = BSL[nb]; bl[1] = BSL[nb + 4];
            mma_bf16(acc[nt], ah, bh);
            mma_bf16(acc[nt], ah, bl);
            mma_bf16(acc[nt], al, bh);
        }
    }

    int gr0 = row0 + wrow + g;
    int gr1 = gr0 + 8;
#pragma unroll
    for (int nt = 0; nt < NT; nt++) {
        int col = nt * 8 + tq * 2;
        if (gr0 < n)
            *(float2*)(C + (size_t)gr0 * NOUT + col) = make_float2(acc[nt][0], acc[nt][1]);
        if (gr1 < n)
            *(float2*)(C + (size_t)gr1 * NOUT + col) = make_float2(acc[nt][2], acc[nt][3]);
    }
}

// ---------------------------------------------------------------------------
// Layer-1 gather: warp per destination node, 128 feats, 4-wide edge unroll.
// ---------------------------------------------------------------------------
__global__ void k_gather128(const float* __restrict__ h, const float* __restrict__ b1,
                            float* __restrict__ out, int n) {
    int node = blockIdx.x * 8 + (threadIdx.x >> 5);
    int lane = threadIdx.x & 31;
    if (node >= n) return;

    float dd = g_dinv[node];
    float self = dd * dd;
    float4 acc0 = ((const float4*)(h + (size_t)node * 128))[lane];
    acc0.x *= self; acc0.y *= self; acc0.z *= self; acc0.w *= self;
    float4 acc1 = make_float4(0.f, 0.f, 0.f, 0.f);

    int e = g_off[node];
    const int end = g_off[node + 1];

    for (; e + 3 < end; e += 4) {
        int s0 = g_csr[e],     s1 = g_csr[e + 1];
        int s2 = g_csr[e + 2], s3 = g_csr[e + 3];
        float w0 = g_csn[e] * dd,     w1 = g_csn[e + 1] * dd;
        float w2 = g_csn[e + 2] * dd, w3 = g_csn[e + 3] * dd;
        float4 v0 = ((const float4*)(h + (size_t)s0 * 128))[lane];
        float4 v1 = ((const float4*)(h + (size_t)s1 * 128))[lane];
        float4 v2 = ((const float4*)(h + (size_t)s2 * 128))[lane];
        float4 v3 = ((const float4*)(h + (size_t)s3 * 128))[lane];
        acc0.x += v0.x * w0; acc0.y += v0.y * w0; acc0.z += v0.z * w0; acc0.w += v0.w * w0;
        acc1.x += v1.x * w1; acc1.y += v1.y * w1; acc1.z += v1.z * w1; acc1.w += v1.w * w1;
        acc0.x += v2.x * w2; acc0.y += v2.y * w2; acc0.z += v2.z * w2; acc0.w += v2.w * w2;
        acc1.x += v3.x * w3; acc1.y += v3.y * w3; acc1.z += v3.z * w3; acc1.w += v3.w * w3;
    }
    for (; e < end; ++e) {
        int s = g_csr[e];
        float w = g_csn[e] * dd;
        float4 v = ((const float4*)(h + (size_t)s * 128))[lane];
        acc0.x += v.x * w; acc0.y += v.y * w; acc0.z += v.z * w; acc0.w += v.w * w;
    }

    float4 bb = ((const float4*)b1)[lane];
    acc0.x = fmaxf(acc0.x + acc1.x + bb.x, 0.f);
    acc0.y = fmaxf(acc0.y + acc1.y + bb.y, 0.f);
    acc0.z = fmaxf(acc0.z + acc1.z + bb.z, 0.f);
    acc0.w = fmaxf(acc0.w + acc1.w + bb.w, 0.f);
    ((float4*)(out + (size_t)node * 128))[lane] = acc0;
}

// ---------------------------------------------------------------------------
// Layer-2 gather + bias + log_softmax: half-warp per node, 4-wide unroll.
// ---------------------------------------------------------------------------
__global__ void k_gather64_lsm(const float* __restrict__ h, const float* __restrict__ b2,
                               float* __restrict__ out, int n) {
    int node = blockIdx.x * 16 + (threadIdx.x >> 4);
    int lane = threadIdx.x & 15;
    if (node >= n) return;

    float dd = g_dinv[node];
    float self = dd * dd;
    float4 acc0 = ((const float4*)(h + (size_t)node * 64))[lane];
    acc0.x *= self; acc0.y *= self; acc0.z *= self; acc0.w *= self;
    float4 acc1 = make_float4(0.f, 0.f, 0.f, 0.f);

    int e = g_off[node];
    const int end = g_off[node + 1];

    for (; e + 3 < end; e += 4) {
        int s0 = g_csr[e],     s1 = g_csr[e + 1];
        int s2 = g_csr[e + 2], s3 = g_csr[e + 3];
        float w0 = g_csn[e] * dd,     w1 = g_csn[e + 1] * dd;
        float w2 = g_csn[e + 2] * dd, w3 = g_csn[e + 3] * dd;
        float4 v0 = ((const float4*)(h + (size_t)s0 * 64))[lane];
        float4 v1 = ((const float4*)(h + (size_t)s1 * 64))[lane];
        float4 v2 = ((const float4*)(h + (size_t)s2 * 64))[lane];
        float4 v3 = ((const float4*)(h + (size_t)s3 * 64))[lane];
        acc0.x += v0.x * w0; acc0.y += v0.y * w0; acc0.z += v0.z * w0; acc0.w += v0.w * w0;
        acc1.x += v1.x * w1; acc1.y += v1.y * w1; acc1.z += v1.z * w1; acc1.w += v1.w * w1;
        acc0.x += v2.x * w2; acc0.y += v2.y * w2; acc0.z += v2.z * w2; acc0.w += v2.w * w2;
        acc1.x += v3.x * w3; acc1.y += v3.y * w3; acc1.z += v3.z * w3; acc1.w += v3.w * w3;
    }
    for (; e < end; ++e) {
        int s = g_csr[e];
        float w = g_csn[e] * dd;
        float4 v = ((const float4*)(h + (size_t)s * 64))[lane];
        acc0.x += v.x * w; acc0.y += v.y * w; acc0.z += v.z * w; acc0.w += v.w * w;
    }

    float4 bb = ((const float4*)b2)[lane];
    acc0.x += acc1.x + bb.x; acc0.y += acc1.y + bb.y;
    acc0.z += acc1.z + bb.z; acc0.w += acc1.w + bb.w;

    float m = fmaxf(fmaxf(acc0.x, acc0.y), fmaxf(acc0.z, acc0.w));
#pragma unroll
    for (int o = 8; o; o >>= 1) m = fmaxf(m, __shfl_xor_sync(0xFFFFFFFFu, m, o));
    float sum = __expf(acc0.x - m) + __expf(acc0.y - m) + __expf(acc0.z - m) + __expf(acc0.w - m);
#pragma unroll
    for (int o = 8; o; o >>= 1) sum += __shfl_xor_sync(0xFFFFFFFFu, sum, o);
    float lse = __logf(sum) + m;

    ((float4*)(out + (size_t)node * 64))[lane] =
        make_float4(acc0.x - lse, acc0.y - lse, acc0.z - lse, acc0.w - lse);
}

// ---------------------------------------------------------------------------
extern "C" void kernel_launch(void* const* d_in, const int* in_sizes, int n_in,
                              void* d_out, int out_size) {
    const float* x  = (const float*)d_in[0];
    const float* W1 = (const float*)d_in[1];
    const float* b1 = (const float*)d_in[2];
    const float* W2 = (const float*)d_in[3];
    const float* b2 = (const float*)d_in[4];
    const int*   ei = (const int*)d_in[5];

    const int n = in_sizes[0] / 128;
    const int E = in_sizes[5] / 2;
    const int* src = ei;
    const int* dst = ei + E;
    float* out = (float*)d_out;

    float* h1   = nullptr; cudaGetSymbolAddress((void**)&h1, g_h1);
    float* out1 = nullptr; cudaGetSymbolAddress((void**)&out1, g_out1);
    float* h2   = nullptr; cudaGetSymbolAddress((void**)&h2, g_h2);
    int*   degp = nullptr; cudaGetSymbolAddress((void**)&degp, g_deg);
    __nv_bfloat16 *w1h, *w1l, *w2h, *w2l;
    cudaGetSymbolAddress((void**)&w1h, g_w1h);
    cudaGetSymbolAddress((void**)&w1l, g_w1l);
    cudaGetSymbolAddress((void**)&w2h, g_w2h);
    cudaGetSymbolAddress((void**)&w2l, g_w2l);

    const int T = 256;
    const int nb = (n + 1023) / 1024;

    constexpr int SM1 = (2 * 128 * STRIDE_W + 2 * 128 * STRIDE_W) * 4;
    constexpr int SM2 = (2 * 128 * STRIDE_W + 2 * 64 * STRIDE_W) * 4;
    cudaFuncSetAttribute(gemm_mma<128>, cudaFuncAttributeMaxDynamicSharedMemorySize, SM1);
    cudaFuncSetAttribute(gemm_mma<64>,  cudaFuncAttributeMaxDynamicSharedMemorySize, SM2);

    // One-time stream/event creation (host-side resources only)
    static cudaStream_t s2 = nullptr;
    static cudaEvent_t evFork = nullptr, evJoin = nullptr;
    if (!s2) {
        cudaStreamCreateWithFlags(&s2, cudaStreamNonBlocking);
        cudaEventCreateWithFlags(&evFork, cudaEventDisableTiming);
        cudaEventCreateWithFlags(&evJoin, cudaEventDisableTiming);
    }

    // Fork: GEMM1 path (prep_w -> gemm1) runs on s2, concurrent with CSR build
    cudaEventRecord(evFork, 0);
    cudaStreamWaitEvent(s2, evFork, 0);

    // s2: weight prep + layer-1 GEMM (depends only on x, W1, W2)
    k_prep_w<<<(128 * 128 + 128 * 64 + T - 1) / T, T, 0, s2>>>(W1, W2);
    const int gb = (n + 127) / 128;
    gemm_mma<128><<<gb, T, SM1, s2>>>(x, w1h, w1l, h1, n);
    cudaEventRecord(evJoin, s2);

    // main stream: CSR build
    cudaMemsetAsync(degp, 0, n * sizeof(int));
    k_hist<<<(E + T - 1) / T, T>>>(dst, E);
    k_dinv<<<(n + T - 1) / T, T>>>(n);
    k_scan1<<<nb, 1024>>>(n);
    k_scan2<<<1, 128>>>(nb);
    k_scan3<<<(n + T - 1) / T, T>>>(n, E);
    k_fill<<<(E + T - 1) / T, T>>>(src, dst, E);

    // Join: gather needs both CSR and gemm1 output
    cudaStreamWaitEvent(0, evJoin, 0);

    k_gather128<<<(n + 7) / 8, T>>>(h1, b1, out1, n);
    gemm_mma<64><<<gb, T, SM2>>>(out1, w2h, w2l, h2, n);
    k_gather64_lsm<<<(n + 15) / 16, T>>>(h2, b2, out, n);
}